// round 4
// baseline (speedup 1.0000x reference)
#include <cuda_runtime.h>
#include <cuda_bf16.h>

// PyramidROIAlign: output [B,N,7,7,256] f32, levels p2..p5 (256/128/64/32), NHWC.
// R4: one WARP per (roi, py) row of the 7x7 pool grid; unrolled loop over the
// 7 px cells. ROI-level + y-dependent setup (box, level select, log2, y-coords)
// amortized 7x; adjacent-px corner reuse now hits in-warp (L1).
// Each lane handles 2 float4s of channels (lane, lane+32).

#define POOLX 7
#define C4N 64   // 256 ch / 4

__global__ __launch_bounds__(256, 4) void roi_align_row_kernel(
    const float* __restrict__ boxes,   // [M,4]  (y1,x1,y2,x2)
    const float* __restrict__ meta,    // [B,93]
    const float* __restrict__ p2,
    const float* __restrict__ p3,
    const float* __restrict__ p4,
    const float* __restrict__ p5,
    float* __restrict__ out,
    int totalWarps, int N)
{
    int gw   = (blockIdx.x * blockDim.x + threadIdx.x) >> 5;  // warp id = (roi,py)
    int lane = threadIdx.x & 31;
    if (gw >= totalWarps) return;

    int py  = gw % POOLX;
    int roi = gw / POOLX;
    int b   = roi / N;

    // ---- per-warp (per roi,py) setup ----
    float4 bx = __ldg(((const float4*)boxes) + roi);
    float y1 = bx.x, x1 = bx.y, y2 = bx.z, x2 = bx.w;
    float h = y2 - y1, w = x2 - x1;

    float area  = __ldg(meta + 4) * __ldg(meta + 5);
    float scale = sqrtf(fmaxf(h * w, 1e-12f));
    float rl    = log2f(scale * sqrtf(area) / 224.0f);
    int lvl = 4 + (int)rintf(rl);
    lvl = min(max(lvl, 2), 5);

    const float* fmap;
    int H;
    if      (lvl == 2) { fmap = p2; H = 256; }
    else if (lvl == 3) { fmap = p3; H = 128; }
    else if (lvl == 4) { fmap = p4; H = 64;  }
    else               { fmap = p5; H = 32;  }
    const int W = H;

    // y interpolation (shared by all 7 px cells)
    float ty = (float)py * (1.0f / 6.0f);
    float ys = (y1 + ty * h) * (float)(H - 1);
    float fy = floorf(ys);
    float ly = ys - fy;
    int y0  = min(max((int)fy,     0), H - 1);
    int y1i = min(max((int)fy + 1, 0), H - 1);

    int rowT = (b * H + y0 ) * W;
    int rowB = (b * H + y1i) * W;

    float xsc = (x1) * (float)(W - 1);          // xs = xsc + tx * w * (W-1)
    float xst = w * (float)(W - 1) * (1.0f / 6.0f);

    const float4* f4 = (const float4*)fmap;
    float4* obase = (float4*)out + (long)gw * (POOLX * C4N) + lane;

    #pragma unroll
    for (int px = 0; px < POOLX; px++) {
        float xs = xsc + (float)px * xst;
        float fx = floorf(xs);
        float lx = xs - fx;
        int x0  = min(max((int)fx,     0), W - 1);
        int x1i = min(max((int)fx + 1, 0), W - 1);

        float w11 = ly * lx;
        float w01 = lx - w11;              // lx*(1-ly)
        float w10 = ly - w11;              // ly*(1-lx)
        float w00 = 1.0f - lx - w10;       // (1-lx)*(1-ly)

        int o00 = (rowT + x0 ) * C4N + lane;
        int o01 = (rowT + x1i) * C4N + lane;
        int o10 = (rowB + x0 ) * C4N + lane;
        int o11 = (rowB + x1i) * C4N + lane;

        float4 a00 = __ldg(f4 + o00);
        float4 a01 = __ldg(f4 + o01);
        float4 a10 = __ldg(f4 + o10);
        float4 a11 = __ldg(f4 + o11);
        float4 b00 = __ldg(f4 + o00 + 32);
        float4 b01 = __ldg(f4 + o01 + 32);
        float4 b10 = __ldg(f4 + o10 + 32);
        float4 b11 = __ldg(f4 + o11 + 32);

        float4 ra, rb;
        ra.x = a00.x*w00 + a01.x*w01 + a10.x*w10 + a11.x*w11;
        ra.y = a00.y*w00 + a01.y*w01 + a10.y*w10 + a11.y*w11;
        ra.z = a00.z*w00 + a01.z*w01 + a10.z*w10 + a11.z*w11;
        ra.w = a00.w*w00 + a01.w*w01 + a10.w*w10 + a11.w*w11;
        rb.x = b00.x*w00 + b01.x*w01 + b10.x*w10 + b11.x*w11;
        rb.y = b00.y*w00 + b01.y*w01 + b10.y*w10 + b11.y*w11;
        rb.z = b00.z*w00 + b01.z*w01 + b10.z*w10 + b11.z*w11;
        rb.w = b00.w*w00 + b01.w*w01 + b10.w*w10 + b11.w*w11;

        __stcs(obase + px * C4N,      ra);
        __stcs(obase + px * C4N + 32, rb);
    }
}

extern "C" void kernel_launch(void* const* d_in, const int* in_sizes, int n_in,
                              void* d_out, int out_size) {
    const float* boxes = (const float*)d_in[0];
    const float* meta  = (const float*)d_in[1];
    const float* p2    = (const float*)d_in[2];
    const float* p3    = (const float*)d_in[3];
    const float* p4    = (const float*)d_in[4];
    const float* p5    = (const float*)d_in[5];
    float* out = (float*)d_out;

    int B = in_sizes[1] / 93;              // image_meta [B,93]
    if (B <= 0) B = 2;
    int N = in_sizes[0] / (4 * B);         // boxes [B,N,4]
    int M = B * N;
    int totalWarps = M * POOLX;            // one warp per (roi, py)

    int threads = 256;                      // 8 warps per block
    int warpsPerBlock = threads / 32;
    int blocks = (totalWarps + warpsPerBlock - 1) / warpsPerBlock;
    roi_align_row_kernel<<<blocks, threads>>>(boxes, meta, p2, p3, p4, p5, out,
                                              totalWarps, N);
}